// round 15
// baseline (speedup 1.0000x reference)
#include <cuda_runtime.h>

// ---------------------------------------------------------------------------
// SLAYER SNN forward on GB300 (sm_103a), fp32, exact-order IIR.
// pool4 -> psp -> conv5x5(2->32) -> [psp+pool2+psp fused] ->
//   EVENT-DRIVEN conv3x3(32->64) -> [psp+pool2+psp fused] ->
//   conv3x3(64->64) -> psp -> fc(4096->256, f-split) -> psp(sum partials) ->
//   fc(256->11) -> psp.   N=4, T=300, stride TP=320.
// Dense MAC kernels: fma.rn.f32x2 + float4 loads.
// conv2 is event-driven: lanes-over-oc, ic-bitmask gather. Bitwise identical
// to dense (same ky->kx->ic order; fma(1,w,acc)==fadd; zeros are exact no-ops).
// ---------------------------------------------------------------------------

#define T  300
#define TP 320
#define NB 4

#define A_SR 0.90483741803595957f   // exp(-1/10)
#define A_RF 0.36787944117144233f   // exp(-1)
#define C_SR 0.27182818284590452f   // e/10
#define C_RF -54.365636569180902f   // -2*10*e
#define THETA 10.0f

typedef unsigned long long u64;

// ---------------- scratch offsets (floats), stride TP ----------------
static const size_t OFF_P0   = 0;         // 4*2*32*32*320  = 2,621,440
static const size_t OFF_S0   = 2621440;   // 2,621,440
static const size_t OFF_A1   = 5242880;   // 4*32*32*32*320 = 41,943,040
static const size_t OFF_S2   = 47185920;  // 4*32*16*16*320 = 10,485,760
static const size_t OFF_A3   = 57671680;  // 4*64*16*16*320 = 20,971,520
static const size_t OFF_S4   = 78643200;  // 4*64*8*8*320   = 5,242,880
static const size_t OFF_A5   = 83886080;  // 5,242,880
static const size_t OFF_S5   = 89128960;  // 5,242,880
static const size_t OFF_A6P  = 94371840;  // 4 partials * 4*256*320 = 1,310,720
static const size_t OFF_S6   = 95682560;  // 327,680
static const size_t OFF_A7   = 96010240;  // 4*11*320 = 14,080
static const size_t OFF_W2T  = 96024320;  // 9*32*64 = 18,432 (transposed w2)
static const size_t OFF_MASK2= 96042752;  // 4*256*320 u32 = 327,680
// total 96,370,432 floats = 385.5 MB
__device__ float g_buf[96370432];

static const int PARTSZ = NB * 256 * TP;   // 327,680

// ---------------- f32x2 helpers ----------------
__device__ __forceinline__ u64 pack2(float a, float b) {
    u64 r; asm("mov.b64 %0, {%1, %2};" : "=l"(r) : "f"(a), "f"(b)); return r;
}
__device__ __forceinline__ float2 unpk(u64 d) {
    float2 r; asm("mov.b64 {%0, %1}, %2;" : "=f"(r.x), "=f"(r.y) : "l"(d)); return r;
}
__device__ __forceinline__ void fma2(u64 &d, u64 a, u64 b) {
    asm("fma.rn.f32x2 %0, %1, %2, %0;" : "+l"(d) : "l"(a), "l"(b));
}

// ---------------- IIR step (exact op order) ----------------
__device__ __forceinline__ float iir_step(float &gp, float &hp, float &gr, float &hr,
                                          float xi)
{
    hp = __fmul_rn(A_SR, __fadd_rn(hp, gp));
    gp = __fadd_rn(__fmul_rn(A_SR, gp), xi);
    hr = __fmul_rn(A_RF, __fadd_rn(hr, gr));
    gr = __fmul_rn(A_RF, gr);
    float u = __fadd_rn(__fmul_rn(C_SR, hp), __fmul_rn(C_RF, hr));
    float s = (u >= THETA) ? 1.0f : 0.0f;
    gr = __fadd_rn(gr, s);
    return s;
}

// ---------------- sum pool (x 1.1*theta), float2 ----------------
template<int K>
__global__ __launch_bounds__(160) void pool_kernel(
    const float* __restrict__ src, float* __restrict__ dst,
    int C, int HO, int WO, int srcStride)
{
    int idx = blockIdx.x;
    int x = idx % WO; int r = idx / WO;
    int y = r % HO;   r /= HO;
    int c = r % C;    int n = r / C;
    const int WI = WO * K;
    const int HI = HO * K;
    const int t = threadIdx.x * 2;
    if (t >= T) return;
    const float* sp = src + (((((size_t)n * C + c) * HI + (size_t)y * K) * WI)
                             + (size_t)x * K) * srcStride + t;
    float sa = 0.f, sb = 0.f;
    #pragma unroll
    for (int i = 0; i < K; i++)
        #pragma unroll
        for (int j = 0; j < K; j++) {
            float2 v = *(const float2*)(sp + ((size_t)i * WI + j) * srcStride);
            sa += v.x; sb += v.y;
        }
    float2 o; o.x = 11.0f * sa; o.y = 11.0f * sb;
    *(float2*)(dst + (size_t)idx * TP + t) = o;
}

// ---------------- plain psp (+optional partial-sum input) ----------------
template<int NPARTS>
__global__ __launch_bounds__(128) void psp_kernel(
    const float* __restrict__ src, float* __restrict__ dst,
    int nNeurons, int dstStride, int partStride)
{
    __shared__ float buf[4][32][65];
    const int warp = threadIdx.x >> 5, lane = threadIdx.x & 31;
    const int base = (blockIdx.x * 4 + warp) * 32;
    if (base >= nNeurons) return;

    float gp = 0.f, hp = 0.f, gr = 0.f, hr = 0.f;

    for (int tt = 0; tt < TP; tt += 64) {
        #pragma unroll
        for (int j = 0; j < 32; j++) {
            int ni = base + j;
            float2 v; v.x = 0.f; v.y = 0.f;
            if (ni < nNeurons && tt + 2 * lane < T) {
                const float* p = src + (size_t)ni * TP + tt + 2 * lane;
                v = *(const float2*)p;
                #pragma unroll
                for (int q = 1; q < NPARTS; q++) {
                    float2 w = *(const float2*)(p + (size_t)q * partStride);
                    v.x += w.x; v.y += w.y;
                }
            }
            buf[warp][j][2 * lane]     = v.x;
            buf[warp][j][2 * lane + 1] = v.y;
        }
        __syncwarp();
        #pragma unroll 4
        for (int k = 0; k < 64; k++) {
            float s = 0.f;
            if (tt + k < T)
                s = iir_step(gp, hp, gr, hr, buf[warp][lane][k]);
            buf[warp][lane][k] = s;
        }
        __syncwarp();
        #pragma unroll
        for (int j = 0; j < 32; j++) {
            int ni = base + j;
            if (ni < nNeurons && tt + 2 * lane < dstStride) {
                float2 v;
                v.x = buf[warp][j][2 * lane];
                v.y = buf[warp][j][2 * lane + 1];
                *(float2*)(dst + (size_t)ni * dstStride + tt + 2 * lane) = v;
            }
        }
        __syncwarp();
    }
}

// ---------------- fused psp -> pool2 -> psp (warp + shuffle) ----------
__global__ __launch_bounds__(128) void psppool_kernel(
    const float* __restrict__ src, float* __restrict__ dst,
    int C, int HO, int WO)
{
    __shared__ float bufS[4][32][65];
    __shared__ float bufP[4][8][65];
    const int warp = threadIdx.x >> 5, lane = threadIdx.x & 31;
    const int pb = (blockIdx.x * 4 + warp) * 8;

    int pi = pb + (lane >> 2);
    int x = pi % WO; int rr = pi / WO;
    int y = rr % HO; rr /= HO;
    int c = rr % C;  int n = rr / C;
    const int HI = 2 * HO, WI = 2 * WO;
    int srow = ((n * C + c) * HI + 2 * y + ((lane >> 1) & 1)) * WI
               + 2 * x + (lane & 1);

    float gp = 0.f, hp = 0.f, gr = 0.f, hr = 0.f;
    float gp2 = 0.f, hp2 = 0.f, gr2 = 0.f, hr2 = 0.f;

    for (int tt = 0; tt < TP; tt += 64) {
        #pragma unroll
        for (int j = 0; j < 32; j++) {
            int r = __shfl_sync(0xffffffffu, srow, j);
            float2 v = *(const float2*)(src + (size_t)r * TP + tt + 2 * lane);
            bufS[warp][j][2 * lane]     = v.x;
            bufS[warp][j][2 * lane + 1] = v.y;
        }
        __syncwarp();
        #pragma unroll 4
        for (int k = 0; k < 64; k++) {
            float s2 = 0.f;
            if (tt + k < T) {
                float s = iir_step(gp, hp, gr, hr, bufS[warp][lane][k]);
                float sm = s + __shfl_xor_sync(0xffffffffu, s, 1);
                sm = sm + __shfl_xor_sync(0xffffffffu, sm, 2);
                s2 = iir_step(gp2, hp2, gr2, hr2, __fmul_rn(11.0f, sm));
            }
            if ((lane & 3) == 0) bufP[warp][lane >> 2][k] = s2;
        }
        __syncwarp();
        #pragma unroll
        for (int j2 = 0; j2 < 8; j2++) {
            float2 v;
            v.x = bufP[warp][j2][2 * lane];
            v.y = bufP[warp][j2][2 * lane + 1];
            *(float2*)(dst + (size_t)(pb + j2) * TP + tt + 2 * lane) = v;
        }
        __syncwarp();
    }
}

// ---------------- dense per-timestep 2D conv (conv1, conv3) ----------------
template<int IC, int K, int PAD, int G>
__global__ __launch_bounds__(128) void conv_kernel(
    const float* __restrict__ src, float* __restrict__ dst,
    const float* __restrict__ w, int H, int W)
{
    constexpr int KK = K * K;
    constexpr int ICKK = IC * KK;
    __shared__ u64 swd[2 * G * ICKK];

    const int lane = threadIdx.x & 31;
    const int warp = threadIdx.x >> 5;
    const int n  = blockIdx.z;
    const int OC = gridDim.y * 2 * G;

    for (int i = threadIdx.x; i < 2 * G * ICKK; i += 128) {
        float v = w[(size_t)blockIdx.y * 2 * G * ICKK + i];
        swd[i] = pack2(v, v);
    }
    __syncthreads();

    const int pixel = blockIdx.x * 2 + (warp & 1);
    const int ocg   = blockIdx.y * 2 + (warp >> 1);
    const u64* wslice = swd + (size_t)(warp >> 1) * G * ICKK;
    const int x = pixel % W, y = pixel / W;

    u64 acc[5][G];
    #pragma unroll
    for (int j = 0; j < 5; j++)
        #pragma unroll
        for (int g = 0; g < G; g++) acc[j][g] = 0ull;

    const float* sb = src + ((size_t)n * IC * H * W) * TP;

    #pragma unroll
    for (int ky = 0; ky < K; ky++) {
        int iy = y + ky - PAD;
        if (iy < 0 || iy >= H) continue;
        #pragma unroll
        for (int kx = 0; kx < K; kx++) {
            int ix = x + kx - PAD;
            if (ix < 0 || ix >= W) continue;
            const float* tap = sb + (size_t)(iy * W + ix) * TP;
            #pragma unroll (IC <= 4 ? IC : 2)
            for (int ic = 0; ic < IC; ic++) {
                const float* p = tap + (size_t)ic * H * W * TP;
                ulonglong2 vA = *(const ulonglong2*)(p + 4 * lane);
                ulonglong2 vB = *(const ulonglong2*)(p + 128 + 4 * lane);
                u64 vC = *(const u64*)(p + 256 + 2 * lane);
                u64 v[5]; v[0] = vA.x; v[1] = vA.y; v[2] = vB.x; v[3] = vB.y; v[4] = vC;
                #pragma unroll
                for (int g = 0; g < G; g++) {
                    u64 wv = wslice[g * ICKK + ic * KK + ky * K + kx];
                    #pragma unroll
                    for (int j = 0; j < 5; j++)
                        fma2(acc[j][g], v[j], wv);
                }
            }
        }
    }

    float* dp = dst + ((size_t)(n * OC + ocg * G) * H * W + pixel) * TP;
    #pragma unroll
    for (int g = 0; g < G; g++) {
        float* base = dp + (size_t)g * H * W * TP;
        ulonglong2 oA; oA.x = acc[0][g]; oA.y = acc[1][g];
        ulonglong2 oB; oB.x = acc[2][g]; oB.y = acc[3][g];
        *(ulonglong2*)(base + 4 * lane) = oA;
        *(ulonglong2*)(base + 128 + 4 * lane) = oB;
        *(u64*)(base + 256 + 2 * lane) = acc[4][g];
    }
}

// ---------------- w2 transpose: [oc][ic][tap] -> [tap][ic][oc] -------------
__global__ __launch_bounds__(256) void w2t_kernel(
    const float* __restrict__ w2, float* __restrict__ w2t)
{
    int i = blockIdx.x * 256 + threadIdx.x;   // 18432 total
    if (i < 9 * 32 * 64) {
        int oc = i & 63, r = i >> 6;          // r = tap*32 + ic
        int ic = r & 31, tap = r >> 5;
        w2t[i] = w2[(oc * 32 + ic) * 9 + tap];
    }
}

// ---------------- S2 -> ic-bitmask [n][px(256)][t(320)] --------------------
__global__ __launch_bounds__(128) void mask2_kernel(
    const float* __restrict__ S2, unsigned* __restrict__ mask)
{
    const int px = blockIdx.x & 255, n = blockIdx.x >> 8;
    for (int t = threadIdx.x; t < TP; t += 128) {
        unsigned m = 0;
        if (t < T) {
            #pragma unroll 8
            for (int c = 0; c < 32; c++) {
                float s = S2[(((size_t)n * 32 + c) * 256 + px) * TP + t];
                if (s != 0.0f) m |= (1u << c);
            }
        }
        mask[((size_t)n * 256 + px) * TP + t] = m;
    }
}

// ---------------- EVENT-DRIVEN conv2: 3x3, 32->64, pad1 --------------------
// Block = 1 output pixel, 8 warps = 8 t-chunks of 40. Warp lanes = 32 oc-pairs
// (oc = 2*lane, 2*lane+1). Per t: iterate 9 taps (ky,kx order), extract active
// ic bits LSB-first, acc += w-pair via fma2 with packed 1.0 — identical op
// sequence to the dense kernel for every output element.
__global__ __launch_bounds__(256) void conv2e_kernel(
    const unsigned* __restrict__ mask,   // [n][256][320]
    const float* __restrict__ w2t,       // [9][32][64]
    float* __restrict__ dst)             // A3 [n][64][256][320]
{
    extern __shared__ float sm[];
    float*    smW = sm;                          // 18432 floats
    unsigned* smM = (unsigned*)(sm + 18432);     // [9][320]
    float*    smS = sm + 18432 + 9 * 320;        // [8 warps][2][32][41]

    const int tid = threadIdx.x;
    const int lane = tid & 31, warp = tid >> 5;
    const int px = blockIdx.x;                   // 0..255
    const int n  = blockIdx.z;
    const int x = px & 15, y = px >> 4;

    for (int i = tid; i < 9 * 32 * 64; i += 256) smW[i] = w2t[i];
    for (int i = tid; i < 9 * 320; i += 256) {
        int tap = i / 320, t = i - tap * 320;
        int ky = tap / 3, kx = tap - ky * 3;
        int iy = y + ky - 1, ix = x + kx - 1;
        unsigned m = 0;
        if (iy >= 0 && iy < 16 && ix >= 0 && ix < 16)
            m = mask[((size_t)n * 256 + iy * 16 + ix) * TP + t];
        smM[i] = m;
    }
    __syncthreads();

    const u64 ONE2 = 0x3f8000003f800000ull;      // (1.0f, 1.0f)
    float* stg = smS + warp * (2 * 32 * 41);
    const int t0 = warp * 40;

    for (int tc = 0; tc < 40; tc++) {
        const int t = t0 + tc;
        u64 acc = 0ull;
        #pragma unroll
        for (int tap = 0; tap < 9; tap++) {
            unsigned m = smM[tap * 320 + t];     // warp-uniform
            while (m) {
                int ic = __ffs(m) - 1;
                m &= m - 1;
                u64 wp = *(const u64*)(smW + (tap * 32 + ic) * 64 + 2 * lane);
                fma2(acc, ONE2, wp);
            }
        }
        float2 f = unpk(acc);
        stg[lane * 41 + tc]           = f.x;     // oc even = 2*lane
        stg[32 * 41 + lane * 41 + tc] = f.y;     // oc odd  = 2*lane+1
    }
    __syncwarp();

    float* dp = dst + ((size_t)n * 64 * 256 + px) * TP + t0;
    for (int oc = 0; oc < 64; oc++) {
        const float* sr = stg + (oc & 1) * (32 * 41) + (oc >> 1) * 41;
        if (lane < 20) {
            float2 v; v.x = sr[2 * lane]; v.y = sr[2 * lane + 1];
            *(float2*)(dp + (size_t)oc * 256 * TP + 2 * lane) = v;
        }
    }
}

// ---------------- fully connected, f32x2 packed, optional f-split ----------
template<int G, int CF>
__global__ __launch_bounds__(160) void fc_kernel(
    const float* __restrict__ src, float* __restrict__ dst,
    const float* __restrict__ w, int INF, int OC, int fLen, int partStride)
{
    extern __shared__ u64 swd_fc[];
    const int lane = threadIdx.x & 31, warp = threadIdx.x >> 5;
    const int og = blockIdx.x, n = blockIdx.y, fs = blockIdx.z;
    const int fbase = fs * fLen;
    const int tbase = warp * 64 + lane * 2;

    u64 acc[G];
    #pragma unroll
    for (int g = 0; g < G; g++) acc[g] = 0ull;

    for (int f0 = fbase; f0 < fbase + fLen; f0 += CF) {
        __syncthreads();
        for (int i = threadIdx.x; i < G * CF; i += 160) {
            float v = w[(size_t)(og * G + i / CF) * INF + f0 + (i % CF)];
            swd_fc[i] = pack2(v, v);
        }
        __syncthreads();
        const float* sp = src + ((size_t)n * INF + f0) * TP + tbase;
        for (int f = 0; f < CF; f++) {
            u64 v = *(const u64*)(sp + (size_t)f * TP);
            #pragma unroll
            for (int g = 0; g < G; g++)
                fma2(acc[g], v, swd_fc[g * CF + f]);
        }
    }

    float* dp = dst + (size_t)fs * partStride
                    + ((size_t)n * OC + og * G) * TP + tbase;
    #pragma unroll
    for (int g = 0; g < G; g++)
        *(u64*)(dp + (size_t)g * TP) = acc[g];
}

// ---------------------------------------------------------------------------
extern "C" void kernel_launch(void* const* d_in, const int* in_sizes, int n_in,
                              void* d_out, int out_size)
{
    const float* s_in = (const float*)d_in[0];   // (4,2,128,128,300)
    const float* w1   = (const float*)d_in[1];   // (32,2,5,5)
    const float* w2   = (const float*)d_in[2];   // (64,32,3,3)
    const float* w3   = (const float*)d_in[3];   // (64,64,3,3)
    const float* w4a  = (const float*)d_in[4];   // (256,4096)
    const float* w4b  = (const float*)d_in[5];   // (11,256)
    float* out = (float*)d_out;                  // (4,11,300)

    float* buf = nullptr;
    cudaGetSymbolAddress((void**)&buf, g_buf);

    float* P0   = buf + OFF_P0;  float* S0 = buf + OFF_S0;
    float* A1   = buf + OFF_A1;  float* S2 = buf + OFF_S2;
    float* A3   = buf + OFF_A3;  float* S4 = buf + OFF_S4;
    float* A5   = buf + OFF_A5;  float* S5 = buf + OFF_S5;
    float* A6P  = buf + OFF_A6P; float* S6 = buf + OFF_S6;
    float* A7   = buf + OFF_A7;
    float* W2T  = buf + OFF_W2T;
    unsigned* MASK2 = (unsigned*)(buf + OFF_MASK2);

    const int CONV2E_SMEM = (9 * 32 * 64 + 9 * 320 + 8 * 2 * 32 * 41) * 4; // 169,216
    cudaFuncSetAttribute(conv2e_kernel,
                         cudaFuncAttributeMaxDynamicSharedMemorySize, CONV2E_SMEM);
    cudaFuncSetAttribute(fc_kernel<16, 512>,
                         cudaFuncAttributeMaxDynamicSharedMemorySize, 16 * 512 * 8);

    // L0: pool4 (4,2,128,128)->(4,2,32,32), psp
    pool_kernel<4><<<NB * 2 * 32 * 32, 160>>>(s_in, P0, 2, 32, 32, T);
    psp_kernel<1><<<64, 128>>>(P0, S0, NB * 2 * 32 * 32, TP, 0);

    // L1: conv 5x5, 2->32, pad2 ; fused psp+pool2+psp -> S2 (4,32,16,16)
    conv_kernel<2, 5, 2, 8><<<dim3(512, 2, NB), 128>>>(S0, A1, w1, 32, 32);
    psppool_kernel<<<1024, 128>>>(A1, S2, 32, 16, 16);

    // L3: EVENT conv 3x3, 32->64 ; fused psp+pool2+psp -> S4 (4,64,8,8)
    w2t_kernel<<<72, 256>>>(w2, W2T);
    mask2_kernel<<<NB * 256, 128>>>(S2, MASK2);
    conv2e_kernel<<<dim3(256, 1, NB), 256, CONV2E_SMEM>>>(MASK2, W2T, A3);
    psppool_kernel<<<512, 128>>>(A3, S4, 64, 8, 8);

    // L5: conv 3x3, 64->64, pad1 ; psp
    conv_kernel<64, 3, 1, 8><<<dim3(32, 4, NB), 128>>>(S4, A5, w3, 8, 8);
    psp_kernel<1><<<128, 128>>>(A5, S5, NB * 64 * 8 * 8, TP, 0);

    // L6: fc 4096->256 split over f into 4 partials; psp sums partials
    fc_kernel<16, 512><<<dim3(16, NB, 4), 160, 16 * 512 * 8>>>(
        S5, A6P, w4a, 4096, 256, 1024, PARTSZ);
    psp_kernel<4><<<8, 128>>>(A6P, S6, NB * 256, TP, PARTSZ);

    // L7: fc 256->11 ; psp -> out (stride 300)
    fc_kernel<11, 256><<<dim3(1, NB, 1), 160, 11 * 256 * 8>>>(
        S6, A7, w4b, 256, 11, 256, 0);
    psp_kernel<1><<<1, 128>>>(A7, out, NB * 11, T, 0);
}